// round 16
// baseline (speedup 1.0000x reference)
#include <cuda_runtime.h>
#include <cuda_bf16.h>
#include <math.h>
#include <stdint.h>

#define S_LEN 2048
#define DMODEL 2048
#define NH 16
#define HD 128

// ---------------------------------------------------------------------------
// Scratch (__device__ globals; allocation-free rule)
// ---------------------------------------------------------------------------
__device__ float g_Q[S_LEN * DMODEL];
__device__ float g_K[S_LEN * DMODEL];
__device__ float g_V[S_LEN * DMODEL];

__device__ __nv_bfloat16 g_xhi[S_LEN * DMODEL];
__device__ __nv_bfloat16 g_xlo[S_LEN * DMODEL];
__device__ __nv_bfloat16 g_ohi[S_LEN * DMODEL];
__device__ __nv_bfloat16 g_olo[S_LEN * DMODEL];
__device__ __nv_bfloat16 g_wth[4][DMODEL * DMODEL];  // transposed [N][K] hi
__device__ __nv_bfloat16 g_wtl[4][DMODEL * DMODEL];  // transposed [N][K] lo

// Attention operands, head-major
__device__ __nv_bfloat16 g_Qh[NH * S_LEN * HD];   // [h][s][d]
__device__ __nv_bfloat16 g_Ql[NH * S_LEN * HD];
__device__ __nv_bfloat16 g_Kh[NH * S_LEN * HD];
__device__ __nv_bfloat16 g_Kl[NH * S_LEN * HD];
__device__ __nv_bfloat16 g_Vth[NH * HD * S_LEN];  // [h][d][s]
__device__ __nv_bfloat16 g_Vtl[NH * HD * S_LEN];

// ---------------------------------------------------------------------------
// Helpers
// ---------------------------------------------------------------------------
__device__ __forceinline__ void cp16(uint32_t s, const void* g) {
    asm volatile("cp.async.cg.shared.global [%0], [%1], 16;" :: "r"(s), "l"(g) : "memory");
}
__device__ __forceinline__ uint32_t smem_u32(const void* p) {
    uint32_t a;
    asm("{ .reg .u64 t; cvta.to.shared.u64 t, %1; cvt.u32.u64 %0, t; }"
        : "=r"(a) : "l"(p));
    return a;
}
__device__ __forceinline__ void mma16816(float* c, uint32_t a0, uint32_t a1,
                                         uint32_t a2, uint32_t a3,
                                         uint32_t b0, uint32_t b1) {
    asm volatile(
        "mma.sync.aligned.m16n8k16.row.col.f32.bf16.bf16.f32 "
        "{%0,%1,%2,%3}, {%4,%5,%6,%7}, {%8,%9}, {%0,%1,%2,%3};"
        : "+f"(c[0]), "+f"(c[1]), "+f"(c[2]), "+f"(c[3])
        : "r"(a0), "r"(a1), "r"(a2), "r"(a3), "r"(b0), "r"(b1));
}
__device__ __forceinline__ void ldsm_x4(uint32_t& r0, uint32_t& r1,
                                        uint32_t& r2, uint32_t& r3, uint32_t addr) {
    asm volatile("ldmatrix.sync.aligned.m8n8.x4.shared.b16 {%0,%1,%2,%3}, [%4];"
                 : "=r"(r0), "=r"(r1), "=r"(r2), "=r"(r3) : "r"(addr));
}
// packed = {lo16 = lo, hi16 = hi}
__device__ __forceinline__ uint32_t pack_bf16(float lo, float hi) {
    uint32_t r;
    asm("cvt.rn.bf16x2.f32 %0, %1, %2;" : "=r"(r) : "f"(hi), "f"(lo));
    return r;
}
__device__ __forceinline__ float bf16lo_f(uint32_t p) { return __uint_as_float(p << 16); }
__device__ __forceinline__ float bf16hi_f(uint32_t p) { return __uint_as_float(p & 0xFFFF0000u); }

// ---------------------------------------------------------------------------
// Split fp32 -> bf16 hi/lo (elementwise)
// ---------------------------------------------------------------------------
__global__ void split_kernel(const float* __restrict__ src,
                             __nv_bfloat16* __restrict__ hi,
                             __nv_bfloat16* __restrict__ lo) {
    int i = (blockIdx.x * blockDim.x + threadIdx.x) * 4;
    float4 v = *(const float4*)(src + i);
    float vv[4] = {v.x, v.y, v.z, v.w};
#pragma unroll
    for (int j = 0; j < 4; j++) {
        __nv_bfloat16 h = __float2bfloat16(vv[j]);
        hi[i + j] = h;
        lo[i + j] = __float2bfloat16(vv[j] - __bfloat162float(h));
    }
}

// Transpose + split all 4 weights: W [K][N] -> T [N][K] hi/lo, bf16x2 stores.
__global__ void wt_split4_kernel(const float* __restrict__ w0,
                                 const float* __restrict__ w1,
                                 const float* __restrict__ w2,
                                 const float* __restrict__ w3,
                                 __nv_bfloat16* __restrict__ Thi,
                                 __nv_bfloat16* __restrict__ Tlo) {
    __shared__ float tile[64][33];
    int z = blockIdx.z;
    const float* W = (z == 0) ? w0 : (z == 1) ? w1 : (z == 2) ? w2 : w3;
    Thi += (size_t)z * DMODEL * DMODEL;
    Tlo += (size_t)z * DMODEL * DMODEL;
    int n0 = blockIdx.x * 32, k0 = blockIdx.y * 64;
    int tx = threadIdx.x, ty = threadIdx.y;
#pragma unroll
    for (int r = 0; r < 64; r += 8)
        tile[ty + r][tx] = W[(size_t)(k0 + ty + r) * DMODEL + n0 + tx];
    __syncthreads();
#pragma unroll
    for (int r = 0; r < 32; r += 8) {
        int n = n0 + ty + r;
        float v0 = tile[2 * tx][ty + r];
        float v1 = tile[2 * tx + 1][ty + r];
        __nv_bfloat16 h0 = __float2bfloat16(v0);
        __nv_bfloat16 h1 = __float2bfloat16(v1);
        size_t o = (size_t)n * DMODEL + k0 + 2 * tx;
        *(__nv_bfloat162*)&Thi[o] = {h0, h1};
        *(__nv_bfloat162*)&Tlo[o] = {__float2bfloat16(v0 - __bfloat162float(h0)),
                                     __float2bfloat16(v1 - __bfloat162float(h1))};
    }
}

// ---------------------------------------------------------------------------
// HMMA split-bf16 GEMM (R10/R13 mainloop, plain fp32 epilogue only)
// ---------------------------------------------------------------------------
#define BK2 32
#define NCHUNK2 (DMODEL / BK2)
#define TILE_BYTES (128 * 64)             // 8192
#define BUF_STRIDE_B (4 * TILE_BYTES)     // 32768
#define GEMM_SMEM (3 * BUF_STRIDE_B)      // 98304

__device__ __forceinline__ void load_tile_sw(uint32_t sbase, const __nv_bfloat16* g,
                                             int row0, int k0, int tid) {
#pragma unroll
    for (int i = 0; i < 2; i++) {
        int slot = tid + i * 256;
        int row = slot >> 2;
        int j = slot & 3;
        uint32_t dst = sbase + row * 64 + ((j ^ ((row >> 1) & 3)) << 4);
        cp16(dst, g + (size_t)(row0 + row) * DMODEL + k0 + j * 8);
    }
}

__device__ __forceinline__ void load_chunk(uint32_t buf, const __nv_bfloat16* Ahi,
                                           const __nv_bfloat16* Alo,
                                           const __nv_bfloat16* Bhi,
                                           const __nv_bfloat16* Blo,
                                           int m0, int n0, int k0, int tid) {
    load_tile_sw(buf, Ahi, m0, k0, tid);
    load_tile_sw(buf + TILE_BYTES, Alo, m0, k0, tid);
    load_tile_sw(buf + 2 * TILE_BYTES, Bhi, n0, k0, tid);
    load_tile_sw(buf + 3 * TILE_BYTES, Blo, n0, k0, tid);
}

__global__ __launch_bounds__(256, 2) void gemm_hmma(
        const __nv_bfloat16* __restrict__ Ahi,
        const __nv_bfloat16* __restrict__ Alo,
        const __nv_bfloat16* __restrict__ Wh,
        const __nv_bfloat16* __restrict__ Wl,
        float* __restrict__ C0, float* __restrict__ C1, float* __restrict__ C2,
        int zoff) {
    extern __shared__ char smem[];
    uint32_t sb = smem_u32(smem);

    const size_t WSZ = (size_t)DMODEL * DMODEL;
    int z = blockIdx.z;
    const __nv_bfloat16* Bhi = Wh + (size_t)(z + zoff) * WSZ;
    const __nv_bfloat16* Blo = Wl + (size_t)(z + zoff) * WSZ;
    float* C = (z == 0) ? C0 : (z == 1) ? C1 : C2;

    int tid = threadIdx.x;
    int wid = tid >> 5, lane = tid & 31;
    int wm = wid & 1, wn = wid >> 1;
    int g = lane >> 2, tq = lane & 3;
    int n0 = blockIdx.x * 128, m0 = blockIdx.y * 128;

    int a_rin = lane & 15;
    uint32_t a_j0 = lane >> 4;
    uint32_t a_t  = (a_rin >> 1) & 3;
    uint32_t a_rowb = (uint32_t)(wm * 64 + a_rin) * 64;

    int b_rin = ((lane >> 4) << 3) + (lane & 7);
    uint32_t b_j0 = (lane >> 3) & 1;
    uint32_t b_t  = (b_rin >> 1) & 3;
    uint32_t b_rowb = (uint32_t)(wn * 32 + b_rin) * 64;

    float acc[4][4][4];
#pragma unroll
    for (int i = 0; i < 4; i++)
#pragma unroll
        for (int j = 0; j < 4; j++)
#pragma unroll
            for (int k = 0; k < 4; k++) acc[i][j][k] = 0.f;

    load_chunk(sb, Ahi, Alo, Bhi, Blo, m0, n0, 0, tid);
    asm volatile("cp.async.commit_group;" ::: "memory");
    load_chunk(sb + BUF_STRIDE_B, Ahi, Alo, Bhi, Blo, m0, n0, BK2, tid);
    asm volatile("cp.async.commit_group;" ::: "memory");

    int bufc = 0;
    for (int c = 0; c < NCHUNK2; ++c) {
        if (c + 1 < NCHUNK2) {
            asm volatile("cp.async.wait_group 1;" ::: "memory");
        } else {
            asm volatile("cp.async.wait_group 0;" ::: "memory");
        }
        __syncthreads();

        if (c + 2 < NCHUNK2) {
            int nb = bufc + 2; if (nb >= 3) nb -= 3;
            load_chunk(sb + nb * BUF_STRIDE_B, Ahi, Alo, Bhi, Blo,
                       m0, n0, (c + 2) * BK2, tid);
            asm volatile("cp.async.commit_group;" ::: "memory");
        }

        uint32_t bufb = sb + bufc * BUF_STRIDE_B;
        uint32_t tAh = bufb;
        uint32_t tAl = bufb + TILE_BYTES;
        uint32_t tBh = bufb + 2 * TILE_BYTES;
        uint32_t tBl = bufb + 3 * TILE_BYTES;

#pragma unroll
        for (int ks = 0; ks < 2; ks++) {
            uint32_t aoff = a_rowb + (((a_j0 + 2 * ks) ^ a_t) << 4);
            uint32_t boff = b_rowb + (((b_j0 + 2 * ks) ^ b_t) << 4);

            uint32_t ah[4][4], bh[4][2];
#pragma unroll
            for (int mf = 0; mf < 4; mf++)
                ldsm_x4(ah[mf][0], ah[mf][1], ah[mf][2], ah[mf][3],
                        tAh + mf * (16 * 64) + aoff);
#pragma unroll
            for (int nfp = 0; nfp < 2; nfp++)
                ldsm_x4(bh[2 * nfp][0], bh[2 * nfp][1],
                        bh[2 * nfp + 1][0], bh[2 * nfp + 1][1],
                        tBh + nfp * (16 * 64) + boff);
#pragma unroll
            for (int mf = 0; mf < 4; mf++)
#pragma unroll
                for (int nf = 0; nf < 4; nf++)
                    mma16816(acc[mf][nf], ah[mf][0], ah[mf][1], ah[mf][2], ah[mf][3],
                             bh[nf][0], bh[nf][1]);

            uint32_t bl[4][2];
#pragma unroll
            for (int nfp = 0; nfp < 2; nfp++)
                ldsm_x4(bl[2 * nfp][0], bl[2 * nfp][1],
                        bl[2 * nfp + 1][0], bl[2 * nfp + 1][1],
                        tBl + nfp * (16 * 64) + boff);
#pragma unroll
            for (int mf = 0; mf < 4; mf++)
#pragma unroll
                for (int nf = 0; nf < 4; nf++)
                    mma16816(acc[mf][nf], ah[mf][0], ah[mf][1], ah[mf][2], ah[mf][3],
                             bl[nf][0], bl[nf][1]);

            uint32_t al[4][4];
#pragma unroll
            for (int mf = 0; mf < 4; mf++)
                ldsm_x4(al[mf][0], al[mf][1], al[mf][2], al[mf][3],
                        tAl + mf * (16 * 64) + aoff);
#pragma unroll
            for (int mf = 0; mf < 4; mf++)
#pragma unroll
                for (int nf = 0; nf < 4; nf++)
                    mma16816(acc[mf][nf], al[mf][0], al[mf][1], al[mf][2], al[mf][3],
                             bh[nf][0], bh[nf][1]);
        }
        if (++bufc >= 3) bufc -= 3;
    }

#pragma unroll
    for (int mf = 0; mf < 4; mf++) {
#pragma unroll
        for (int nf = 0; nf < 4; nf++) {
            int row = m0 + wm * 64 + mf * 16 + g;
            int col = n0 + wn * 32 + nf * 8 + 2 * tq;
            float2 v0 = {acc[mf][nf][0], acc[mf][nf][1]};
            float2 v1 = {acc[mf][nf][2], acc[mf][nf][3]};
            *(float2*)&C[(size_t)row * DMODEL + col] = v0;
            *(float2*)&C[(size_t)(row + 8) * DMODEL + col] = v1;
        }
    }
}

// ---------------------------------------------------------------------------
// RoPE + split to head-major bf16 hi/lo for Q and K
// ---------------------------------------------------------------------------
__global__ void rope_split_kernel(const float* __restrict__ fcos,
                                  const float* __restrict__ fsin) {
    int p = blockIdx.x * blockDim.x + threadIdx.x;
    int i = p & 63;
    int h = (p >> 6) & 15;
    int s = p >> 10;

    float c  = fcos[s * 64 + i];
    float sn = fsin[s * 64 + i];
    size_t src = (size_t)s * DMODEL + h * HD + 2 * i;
    size_t dst = (size_t)h * (S_LEN * HD) + (size_t)s * HD + 2 * i;

    float q0 = g_Q[src], q1 = g_Q[src + 1];
    float r0 = q0 * c - q1 * sn;
    float r1 = q0 * sn + q1 * c;
    __nv_bfloat16 h0 = __float2bfloat16(r0), h1 = __float2bfloat16(r1);
    *(__nv_bfloat162*)&g_Qh[dst] = {h0, h1};
    *(__nv_bfloat162*)&g_Ql[dst] = {__float2bfloat16(r0 - __bfloat162float(h0)),
                                    __float2bfloat16(r1 - __bfloat162float(h1))};

    float k0 = g_K[src], k1 = g_K[src + 1];
    float t0 = k0 * c - k1 * sn;
    float t1 = k0 * sn + k1 * c;
    __nv_bfloat16 u0 = __float2bfloat16(t0), u1 = __float2bfloat16(t1);
    *(__nv_bfloat162*)&g_Kh[dst] = {u0, u1};
    *(__nv_bfloat162*)&g_Kl[dst] = {__float2bfloat16(t0 - __bfloat162float(u0)),
                                    __float2bfloat16(t1 - __bfloat162float(u1))};
}

// V: [s][h*128+d] fp32 -> Vt [h][d][s] bf16 hi/lo, bf16x2 stores along s.
__global__ void v_split_t_kernel() {
    __shared__ float tile[64][33];
    int s0 = blockIdx.x * 64, d0 = blockIdx.y * 32, h = blockIdx.z;
    int tx = threadIdx.x, ty = threadIdx.y;
#pragma unroll
    for (int r = 0; r < 64; r += 8)
        tile[ty + r][tx] = g_V[(size_t)(s0 + ty + r) * DMODEL + h * HD + d0 + tx];
    __syncthreads();
#pragma unroll
    for (int r = 0; r < 32; r += 8) {
        int d = d0 + ty + r;
        float v0 = tile[2 * tx][ty + r];
        float v1 = tile[2 * tx + 1][ty + r];
        __nv_bfloat16 h0 = __float2bfloat16(v0);
        __nv_bfloat16 h1 = __float2bfloat16(v1);
        size_t o = (size_t)(h * HD + d) * S_LEN + s0 + 2 * tx;
        *(__nv_bfloat162*)&g_Vth[o] = {h0, h1};
        *(__nv_bfloat162*)&g_Vtl[o] = {__float2bfloat16(v0 - __bfloat162float(h0)),
                                       __float2bfloat16(v1 - __bfloat162float(h1))};
    }
}

// ---------------------------------------------------------------------------
// FA2-style HMMA flash attention. R16: BQ=128, 8 warps (256 threads), 1 head
// per CTA. Each warp owns 16 Q rows (identical per-warp structure to R13).
// K/V tiles 64 wide, kb = 0..2*qb+1. Fully-masked tiles contribute exact 0.
// Smem: Q 2*128*272 + K 2*64*272 + V 2*128*144 = 141312 B.
// ---------------------------------------------------------------------------
#define BQA 128
#define QH_B 0
#define QL_B (128 * 272)
#define KH_B (2 * 128 * 272)
#define KL_B (2 * 128 * 272 + 64 * 272)
#define VH_B (2 * 128 * 272 + 2 * 64 * 272)
#define VL_B (2 * 128 * 272 + 2 * 64 * 272 + 128 * 144)
#define ATTN_SMEM (2 * 128 * 272 + 2 * 64 * 272 + 2 * 128 * 144)  // 141312

__global__ __launch_bounds__(256) void attn_hmma() {
    extern __shared__ char smem[];
    uint32_t sb = smem_u32(smem);

    int tid = threadIdx.x;
    int w = tid >> 5, lane = tid & 31;
    int g = lane >> 2, tq = lane & 3;
    int h = blockIdx.y;
    int qb = gridDim.x - 1 - blockIdx.x;     // big tiles first
    int kb_max = 2 * qb + 1;

    const __nv_bfloat16* Qhp = g_Qh + (size_t)h * (S_LEN * HD);
    const __nv_bfloat16* Qlp = g_Ql + (size_t)h * (S_LEN * HD);
    const __nv_bfloat16* Khp = g_Kh + (size_t)h * (S_LEN * HD);
    const __nv_bfloat16* Klp = g_Kl + (size_t)h * (S_LEN * HD);
    const __nv_bfloat16* Vhp = g_Vth + (size_t)h * (HD * S_LEN);
    const __nv_bfloat16* Vlp = g_Vtl + (size_t)h * (HD * S_LEN);

    uint32_t qa_base = (uint32_t)(w * 16 + (lane & 15)) * 272 + (lane >> 4) * 16;
    uint32_t kb_base = (uint32_t)(((lane >> 4) << 3) + (lane & 7)) * 272
                       + ((lane >> 3) & 1) * 16;
    uint32_t vb_base = (uint32_t)(((lane >> 4) << 3) + (lane & 7)) * 144
                       + ((lane >> 3) & 1) * 16;

    // Q tile hi/lo: 128 rows x 16 chunks = 2048 slots, 256 threads -> 8 iters
#pragma unroll
    for (int i = 0; i < 8; i++) {
        int slot = tid + i * 256;
        int row = slot >> 4, j = slot & 15;
        cp16(sb + QH_B + row * 272 + j * 16,
             Qhp + (size_t)(qb * BQA + row) * HD + j * 8);
    }
#pragma unroll
    for (int i = 0; i < 8; i++) {
        int slot = tid + i * 256;
        int row = slot >> 4, j = slot & 15;
        cp16(sb + QL_B + row * 272 + j * 16,
             Qlp + (size_t)(qb * BQA + row) * HD + j * 8);
    }
    asm volatile("cp.async.commit_group;" ::: "memory");

    // K_0 (64 x 16 = 1024 slots -> 4 iters)
#pragma unroll
    for (int i = 0; i < 4; i++) {
        int slot = tid + i * 256;
        int row = slot >> 4, j = slot & 15;
        cp16(sb + KH_B + row * 272 + j * 16, Khp + (size_t)row * HD + j * 8);
    }
#pragma unroll
    for (int i = 0; i < 4; i++) {
        int slot = tid + i * 256;
        int row = slot >> 4, j = slot & 15;
        cp16(sb + KL_B + row * 272 + j * 16, Klp + (size_t)row * HD + j * 8);
    }
    asm volatile("cp.async.commit_group;" ::: "memory");
    // V_0 (128 x 8 = 1024 slots -> 4 iters)
#pragma unroll
    for (int i = 0; i < 4; i++) {
        int slot = tid + i * 256;
        int row = slot >> 3, j = slot & 7;
        cp16(sb + VH_B + row * 144 + j * 16, Vhp + (size_t)row * S_LEN + j * 8);
    }
#pragma unroll
    for (int i = 0; i < 4; i++) {
        int slot = tid + i * 256;
        int row = slot >> 3, j = slot & 7;
        cp16(sb + VL_B + row * 144 + j * 16, Vlp + (size_t)row * S_LEN + j * 8);
    }
    asm volatile("cp.async.commit_group;" ::: "memory");

    float of[16][4];
#pragma unroll
    for (int i = 0; i < 16; i++)
#pragma unroll
        for (int j = 0; j < 4; j++) of[i][j] = 0.f;
    float m0 = -INFINITY, m1 = -INFINITY, l0 = 0.f, l1 = 0.f;

    const float inv_sqrt_hd = 0.08838834764831845f;
    const int qrow0 = qb * BQA + w * 16 + g;
    const int qrow1 = qrow0 + 8;

    for (int kb = 0; kb <= kb_max; ++kb) {
        asm volatile("cp.async.wait_group 1;" ::: "memory");
        __syncthreads();

        float sf[8][4];
#pragma unroll
        for (int i = 0; i < 8; i++)
#pragma unroll
            for (int j = 0; j < 4; j++) sf[i][j] = 0.f;

#pragma unroll
        for (int ks = 0; ks < 8; ks++) {
            uint32_t koff = ks * 32;
            uint32_t ah[4], al[4], bh[8][2], bl[8][2];
            ldsm_x4(ah[0], ah[1], ah[2], ah[3], sb + QH_B + qa_base + koff);
            ldsm_x4(al[0], al[1], al[2], al[3], sb + QL_B + qa_base + koff);
#pragma unroll
            for (int nfp = 0; nfp < 4; nfp++)
                ldsm_x4(bh[2 * nfp][0], bh[2 * nfp][1],
                        bh[2 * nfp + 1][0], bh[2 * nfp + 1][1],
                        sb + KH_B + nfp * (16 * 272) + kb_base + koff);
#pragma unroll
            for (int nfp = 0; nfp < 4; nfp++)
                ldsm_x4(bl[2 * nfp][0], bl[2 * nfp][1],
                        bl[2 * nfp + 1][0], bl[2 * nfp + 1][1],
                        sb + KL_B + nfp * (16 * 272) + kb_base + koff);
#pragma unroll
            for (int nf = 0; nf < 8; nf++)
                mma16816(sf[nf], ah[0], ah[1], ah[2], ah[3], bh[nf][0], bh[nf][1]);
#pragma unroll
            for (int nf = 0; nf < 8; nf++)
                mma16816(sf[nf], ah[0], ah[1], ah[2], ah[3], bl[nf][0], bl[nf][1]);
#pragma unroll
            for (int nf = 0; nf < 8; nf++)
                mma16816(sf[nf], al[0], al[1], al[2], al[3], bh[nf][0], bh[nf][1]);
        }
        __syncthreads();

        if (kb + 1 <= kb_max) {
#pragma unroll
            for (int i = 0; i < 4; i++) {
                int slot = tid + i * 256;
                int row = slot >> 4, j = slot & 15;
                cp16(sb + KH_B + row * 272 + j * 16,
                     Khp + (size_t)((kb + 1) * 64 + row) * HD + j * 8);
            }
#pragma unroll
            for (int i = 0; i < 4; i++) {
                int slot = tid + i * 256;
                int row = slot >> 4, j = slot & 15;
                cp16(sb + KL_B + row * 272 + j * 16,
                     Klp + (size_t)((kb + 1) * 64 + row) * HD + j * 8);
            }
        }
        asm volatile("cp.async.commit_group;" ::: "memory");

        float mloc0 = -INFINITY, mloc1 = -INFINITY;
        bool diag = (kb * 64 + 63 > qrow0);
#pragma unroll
        for (int nf = 0; nf < 8; nf++) {
#pragma unroll
            for (int cc = 0; cc < 2; cc++) {
                int kcol = kb * 64 + nf * 8 + 2 * tq + cc;
                float s = sf[nf][cc] * inv_sqrt_hd;
                float t = s * s * 0.0004f;
                s = s * (1.f - t * (0.3333333333f - 0.1333333333f * t));
                if (diag && kcol > qrow0) s = -INFINITY;
                sf[nf][cc] = s;
                mloc0 = fmaxf(mloc0, s);
                float s2 = sf[nf][cc + 2] * inv_sqrt_hd;
                float t2 = s2 * s2 * 0.0004f;
                s2 = s2 * (1.f - t2 * (0.3333333333f - 0.1333333333f * t2));
                if (diag && kcol > qrow1) s2 = -INFINITY;
                sf[nf][cc + 2] = s2;
                mloc1 = fmaxf(mloc1, s2);
            }
        }
        mloc0 = fmaxf(mloc0, __shfl_xor_sync(0xFFFFFFFF, mloc0, 1));
        mloc0 = fmaxf(mloc0, __shfl_xor_sync(0xFFFFFFFF, mloc0, 2));
        mloc1 = fmaxf(mloc1, __shfl_xor_sync(0xFFFFFFFF, mloc1, 1));
        mloc1 = fmaxf(mloc1, __shfl_xor_sync(0xFFFFFFFF, mloc1, 2));

        float mn0 = fmaxf(m0, mloc0), mn1 = fmaxf(m1, mloc1);
        float cf0 = __expf(m0 - mn0), cf1 = __expf(m1 - mn1);
        m0 = mn0; m1 = mn1;

        float ls0 = 0.f, ls1 = 0.f;
#pragma unroll
        for (int nf = 0; nf < 8; nf++) {
#pragma unroll
            for (int cc = 0; cc < 2; cc++) {
                float p = __expf(sf[nf][cc] - mn0);
                sf[nf][cc] = p; ls0 += p;
                float p2 = __expf(sf[nf][cc + 2] - mn1);
                sf[nf][cc + 2] = p2; ls1 += p2;
            }
        }
        ls0 += __shfl_xor_sync(0xFFFFFFFF, ls0, 1);
        ls0 += __shfl_xor_sync(0xFFFFFFFF, ls0, 2);
        ls1 += __shfl_xor_sync(0xFFFFFFFF, ls1, 1);
        ls1 += __shfl_xor_sync(0xFFFFFFFF, ls1, 2);
        l0 = l0 * cf0 + ls0;
        l1 = l1 * cf1 + ls1;

#pragma unroll
        for (int i = 0; i < 16; i++) {
            of[i][0] *= cf0; of[i][1] *= cf0;
            of[i][2] *= cf1; of[i][3] *= cf1;
        }

        asm volatile("cp.async.wait_group 1;" ::: "memory");
        __syncthreads();

#pragma unroll
        for (int ksv = 0; ksv < 4; ksv++) {
            float c00 = sf[2 * ksv][0],     c01 = sf[2 * ksv][1];
            float c02 = sf[2 * ksv][2],     c03 = sf[2 * ksv][3];
            float c10 = sf[2 * ksv + 1][0], c11 = sf[2 * ksv + 1][1];
            float c12 = sf[2 * ksv + 1][2], c13 = sf[2 * ksv + 1][3];
            uint32_t pa0 = pack_bf16(c00, c01);
            uint32_t pa1 = pack_bf16(c02, c03);
            uint32_t pa2 = pack_bf16(c10, c11);
            uint32_t pa3 = pack_bf16(c12, c13);
            uint32_t pl0 = pack_bf16(c00 - bf16lo_f(pa0), c01 - bf16hi_f(pa0));
            uint32_t pl1 = pack_bf16(c02 - bf16lo_f(pa1), c03 - bf16hi_f(pa1));
            uint32_t pl2 = pack_bf16(c10 - bf16lo_f(pa2), c11 - bf16hi_f(pa2));
            uint32_t pl3 = pack_bf16(c12 - bf16lo_f(pa3), c13 - bf16hi_f(pa3));
            uint32_t soff = ksv * 32;
#pragma unroll
            for (int np = 0; np < 4; np++) {
                int n0i = 2 * np;
                uint32_t vhA0, vhA1, vhA2, vhA3, vlA0, vlA1, vlA2, vlA3;
                uint32_t vhB0, vhB1, vhB2, vhB3, vlB0, vlB1, vlB2, vlB3;
                ldsm_x4(vhA0, vhA1, vhA2, vhA3,
                        sb + VH_B + n0i * (16 * 144) + vb_base + soff);
                ldsm_x4(vlA0, vlA1, vlA2, vlA3,
                        sb + VL_B + n0i * (16 * 144) + vb_base + soff);
                ldsm_x4(vhB0, vhB1, vhB2, vhB3,
                        sb + VH_B + (n0i + 1) * (16 * 144) + vb_base + soff);
                ldsm_x4(vlB0, vlB1, vlB2, vlB3,
                        sb + VL_B + (n0i + 1) * (16 * 144) + vb_base + soff);
                float* oA0 = of[2 * n0i];
                float* oA1 = of[2 * n0i + 1];
                float* oB0 = of[2 * n0i + 2];
                float* oB1 = of[2 * n0i + 3];
                mma16816(oA0, pa0, pa1, pa2, pa3, vhA0, vhA1);
                mma16816(oA1, pa0, pa1, pa2, pa3, vhA2, vhA3);
                mma16816(oB0, pa0, pa1, pa2, pa3, vhB0, vhB1);
                mma16816(oB1, pa0, pa1, pa2, pa3, vhB2, vhB3);
                mma16816(oA0, pa0, pa1, pa2, pa3, vlA0, vlA1);
                mma16816(oA1, pa0, pa1, pa2, pa3, vlA2, vlA3);
                mma16816(oB0, pa0, pa1, pa2, pa3, vlB0, vlB1);
                mma16816(oB1, pa0, pa1, pa2, pa3, vlB2, vlB3);
                mma16816(oA0, pl0, pl1, pl2, pl3, vhA0, vhA1);
                mma16816(oA1, pl0, pl1, pl2, pl3, vhA2, vhA3);
                mma16816(oB0, pl0, pl1, pl2, pl3, vhB0, vhB1);
                mma16816(oB1, pl0, pl1, pl2, pl3, vhB2, vhB3);
            }
        }
        __syncthreads();

        if (kb + 1 <= kb_max) {
#pragma unroll
            for (int i = 0; i < 4; i++) {
                int slot = tid + i * 256;
                int row = slot >> 3, j = slot & 7;
                cp16(sb + VH_B + row * 144 + j * 16,
                     Vhp + (size_t)row * S_LEN + (kb + 1) * 64 + j * 8);
            }
#pragma unroll
            for (int i = 0; i < 4; i++) {
                int slot = tid + i * 256;
                int row = slot >> 3, j = slot & 7;
                cp16(sb + VL_B + row * 144 + j * 16,
                     Vlp + (size_t)row * S_LEN + (kb + 1) * 64 + j * 8);
            }
        }
        asm volatile("cp.async.commit_group;" ::: "memory");
    }

    float il0 = 1.f / l0, il1 = 1.f / l1;
#pragma unroll
    for (int nf2 = 0; nf2 < 16; nf2++) {
        int col = h * HD + nf2 * 8 + 2 * tq;
        float o00 = of[nf2][0] * il0, o01 = of[nf2][1] * il0;
        float o10 = of[nf2][2] * il1, o11 = of[nf2][3] * il1;
        __nv_bfloat16 h00 = __float2bfloat16(o00), h01 = __float2bfloat16(o01);
        __nv_bfloat16 h10 = __float2bfloat16(o10), h11 = __float2bfloat16(o11);
        *(__nv_bfloat162*)&g_ohi[(size_t)qrow0 * DMODEL + col] = {h00, h01};
        *(__nv_bfloat162*)&g_ohi[(size_t)qrow1 * DMODEL + col] = {h10, h11};
        *(__nv_bfloat162*)&g_olo[(size_t)qrow0 * DMODEL + col] =
            {__float2bfloat16(o00 - __bfloat162float(h00)),
             __float2bfloat16(o01 - __bfloat162float(h01))};
        *(__nv_bfloat162*)&g_olo[(size_t)qrow1 * DMODEL + col] =
            {__float2bfloat16(o10 - __bfloat162float(h10)),
             __float2bfloat16(o11 - __bfloat162float(h11))};
    }
}

// ---------------------------------------------------------------------------
// Launch
// ---------------------------------------------------------------------------
extern "C" void kernel_launch(void* const* d_in, const int* in_sizes, int n_in,
                              void* d_out, int out_size) {
    const float* x    = (const float*)d_in[0];
    const float* wq   = (const float*)d_in[1];
    const float* wk   = (const float*)d_in[2];
    const float* wv   = (const float*)d_in[3];
    const float* wo   = (const float*)d_in[4];
    const float* fcos = (const float*)d_in[5];
    const float* fsin = (const float*)d_in[6];
    float* out = (float*)d_out;

    float *Qp, *Kp, *Vp;
    __nv_bfloat16 *xhi, *xlo, *ohi, *olo, *wth, *wtl;
    cudaGetSymbolAddress((void**)&Qp, g_Q);
    cudaGetSymbolAddress((void**)&Kp, g_K);
    cudaGetSymbolAddress((void**)&Vp, g_V);
    cudaGetSymbolAddress((void**)&xhi, g_xhi);
    cudaGetSymbolAddress((void**)&xlo, g_xlo);
    cudaGetSymbolAddress((void**)&ohi, g_ohi);
    cudaGetSymbolAddress((void**)&olo, g_olo);
    cudaGetSymbolAddress((void**)&wth, g_wth);
    cudaGetSymbolAddress((void**)&wtl, g_wtl);

    cudaFuncSetAttribute(gemm_hmma, cudaFuncAttributeMaxDynamicSharedMemorySize, GEMM_SMEM);
    cudaFuncSetAttribute(attn_hmma, cudaFuncAttributeMaxDynamicSharedMemorySize, ATTN_SMEM);

    int nElem = S_LEN * DMODEL;

    split_kernel<<<nElem / (256 * 4), 256>>>(x, xhi, xlo);
    wt_split4_kernel<<<dim3(DMODEL / 32, DMODEL / 64, 4), dim3(32, 8)>>>(
        wq, wk, wv, wo, wth, wtl);

    gemm_hmma<<<dim3(DMODEL / 128, DMODEL / 128, 3), 256, GEMM_SMEM>>>(
        xhi, xlo, wth, wtl, Qp, Kp, Vp, 0);

    int pairs = S_LEN * NH * (HD / 2);
    rope_split_kernel<<<pairs / 256, 256>>>(fcos, fsin);
    v_split_t_kernel<<<dim3(S_LEN / 64, HD / 32, NH), dim3(32, 8)>>>();

    attn_hmma<<<dim3(S_LEN / BQA, NH), 256, ATTN_SMEM>>>();

    gemm_hmma<<<dim3(DMODEL / 128, DMODEL / 128, 1), 256, GEMM_SMEM>>>(
        ohi, olo, wth, wtl, out, out, out, 3);
}

// round 17
// speedup vs baseline: 1.2928x; 1.2928x over previous
#include <cuda_runtime.h>
#include <cuda_bf16.h>
#include <cuda_fp16.h>
#include <math.h>
#include <stdint.h>

#define S_LEN 2048
#define DMODEL 2048
#define NH 16
#define HD 128

// ---------------------------------------------------------------------------
// Scratch (__device__ globals; allocation-free rule)
// ---------------------------------------------------------------------------
__device__ float g_Q[S_LEN * DMODEL];
__device__ float g_K[S_LEN * DMODEL];
__device__ float g_V[S_LEN * DMODEL];

__device__ __half g_xhi[S_LEN * DMODEL];
__device__ __half g_xlo[S_LEN * DMODEL];
__device__ __half g_ohi[S_LEN * DMODEL];
__device__ __half g_olo[S_LEN * DMODEL];
__device__ __half g_wth[4][DMODEL * DMODEL];   // transposed [N][K], fp16 hi only

// Attention operands, head-major (bf16 3-term path unchanged)
__device__ __nv_bfloat16 g_Qh[NH * S_LEN * HD];   // [h][s][d]
__device__ __nv_bfloat16 g_Ql[NH * S_LEN * HD];
__device__ __nv_bfloat16 g_Kh[NH * S_LEN * HD];
__device__ __nv_bfloat16 g_Kl[NH * S_LEN * HD];
__device__ __nv_bfloat16 g_Vth[NH * HD * S_LEN];  // [h][d][s]
__device__ __nv_bfloat16 g_Vtl[NH * HD * S_LEN];

// ---------------------------------------------------------------------------
// Helpers
// ---------------------------------------------------------------------------
__device__ __forceinline__ void cp16(uint32_t s, const void* g) {
    asm volatile("cp.async.cg.shared.global [%0], [%1], 16;" :: "r"(s), "l"(g) : "memory");
}
__device__ __forceinline__ uint32_t smem_u32(const void* p) {
    uint32_t a;
    asm("{ .reg .u64 t; cvta.to.shared.u64 t, %1; cvt.u32.u64 %0, t; }"
        : "=r"(a) : "l"(p));
    return a;
}
// bf16 mma (attention)
__device__ __forceinline__ void mma16816(float* c, uint32_t a0, uint32_t a1,
                                         uint32_t a2, uint32_t a3,
                                         uint32_t b0, uint32_t b1) {
    asm volatile(
        "mma.sync.aligned.m16n8k16.row.col.f32.bf16.bf16.f32 "
        "{%0,%1,%2,%3}, {%4,%5,%6,%7}, {%8,%9}, {%0,%1,%2,%3};"
        : "+f"(c[0]), "+f"(c[1]), "+f"(c[2]), "+f"(c[3])
        : "r"(a0), "r"(a1), "r"(a2), "r"(a3), "r"(b0), "r"(b1));
}
// fp16 mma (GEMMs)
__device__ __forceinline__ void mma16816h(float* c, uint32_t a0, uint32_t a1,
                                          uint32_t a2, uint32_t a3,
                                          uint32_t b0, uint32_t b1) {
    asm volatile(
        "mma.sync.aligned.m16n8k16.row.col.f32.f16.f16.f32 "
        "{%0,%1,%2,%3}, {%4,%5,%6,%7}, {%8,%9}, {%0,%1,%2,%3};"
        : "+f"(c[0]), "+f"(c[1]), "+f"(c[2]), "+f"(c[3])
        : "r"(a0), "r"(a1), "r"(a2), "r"(a3), "r"(b0), "r"(b1));
}
__device__ __forceinline__ void ldsm_x4(uint32_t& r0, uint32_t& r1,
                                        uint32_t& r2, uint32_t& r3, uint32_t addr) {
    asm volatile("ldmatrix.sync.aligned.m8n8.x4.shared.b16 {%0,%1,%2,%3}, [%4];"
                 : "=r"(r0), "=r"(r1), "=r"(r2), "=r"(r3) : "r"(addr));
}
// packed = {lo16 = lo, hi16 = hi}  (bf16)
__device__ __forceinline__ uint32_t pack_bf16(float lo, float hi) {
    uint32_t r;
    asm("cvt.rn.bf16x2.f32 %0, %1, %2;" : "=r"(r) : "f"(hi), "f"(lo));
    return r;
}
__device__ __forceinline__ float bf16lo_f(uint32_t p) { return __uint_as_float(p << 16); }
__device__ __forceinline__ float bf16hi_f(uint32_t p) { return __uint_as_float(p & 0xFFFF0000u); }

// ---------------------------------------------------------------------------
// Split fp32 -> fp16 hi/lo (elementwise); lo = fp16(x - fp16(x))
// ---------------------------------------------------------------------------
__global__ void split_kernel(const float* __restrict__ src,
                             __half* __restrict__ hi,
                             __half* __restrict__ lo) {
    int i = (blockIdx.x * blockDim.x + threadIdx.x) * 4;
    float4 v = *(const float4*)(src + i);
    float vv[4] = {v.x, v.y, v.z, v.w};
#pragma unroll
    for (int j = 0; j < 4; j++) {
        __half h = __float2half(vv[j]);
        hi[i + j] = h;
        lo[i + j] = __float2half(vv[j] - __half2float(h));
    }
}

// Transpose all 4 weights: W [K][N] -> T [N][K] fp16 (hi only), half2 stores.
__global__ void wt_split4_kernel(const float* __restrict__ w0,
                                 const float* __restrict__ w1,
                                 const float* __restrict__ w2,
                                 const float* __restrict__ w3,
                                 __half* __restrict__ Thi) {
    __shared__ float tile[64][33];
    int z = blockIdx.z;
    const float* W = (z == 0) ? w0 : (z == 1) ? w1 : (z == 2) ? w2 : w3;
    Thi += (size_t)z * DMODEL * DMODEL;
    int n0 = blockIdx.x * 32, k0 = blockIdx.y * 64;
    int tx = threadIdx.x, ty = threadIdx.y;
#pragma unroll
    for (int r = 0; r < 64; r += 8)
        tile[ty + r][tx] = W[(size_t)(k0 + ty + r) * DMODEL + n0 + tx];
    __syncthreads();
#pragma unroll
    for (int r = 0; r < 32; r += 8) {
        int n = n0 + ty + r;
        float v0 = tile[2 * tx][ty + r];
        float v1 = tile[2 * tx + 1][ty + r];
        size_t o = (size_t)n * DMODEL + k0 + 2 * tx;
        *(__half2*)&Thi[o] = {__float2half(v0), __float2half(v1)};
    }
}

// ---------------------------------------------------------------------------
// HMMA fp16 2-term GEMM: C = (Ah + Al) @ Wh^T.  Tiles: Ah, Al, Bh (24KB/chunk),
// 3-stage cp.async pipeline, ldmatrix, 2 CTAs/SM. blockIdx.z selects weight.
// ---------------------------------------------------------------------------
#define BK2 32
#define NCHUNK2 (DMODEL / BK2)
#define TILE_BYTES (128 * 64)             // 8192
#define BUF_STRIDE_B (3 * TILE_BYTES)     // 24576
#define GEMM_SMEM (3 * BUF_STRIDE_B)      // 73728

__device__ __forceinline__ void load_tile_sw(uint32_t sbase, const __half* g,
                                             int row0, int k0, int tid) {
#pragma unroll
    for (int i = 0; i < 2; i++) {
        int slot = tid + i * 256;
        int row = slot >> 2;
        int j = slot & 3;
        uint32_t dst = sbase + row * 64 + ((j ^ ((row >> 1) & 3)) << 4);
        cp16(dst, g + (size_t)(row0 + row) * DMODEL + k0 + j * 8);
    }
}

__device__ __forceinline__ void load_chunk(uint32_t buf, const __half* Ahi,
                                           const __half* Alo, const __half* Bh,
                                           int m0, int n0, int k0, int tid) {
    load_tile_sw(buf, Ahi, m0, k0, tid);
    load_tile_sw(buf + TILE_BYTES, Alo, m0, k0, tid);
    load_tile_sw(buf + 2 * TILE_BYTES, Bh, n0, k0, tid);
}

__global__ __launch_bounds__(256, 2) void gemm_hmma(
        const __half* __restrict__ Ahi,
        const __half* __restrict__ Alo,
        const __half* __restrict__ Wh,
        float* __restrict__ C0, float* __restrict__ C1, float* __restrict__ C2,
        int zoff) {
    extern __shared__ char smem[];
    uint32_t sb = smem_u32(smem);

    const size_t WSZ = (size_t)DMODEL * DMODEL;
    int z = blockIdx.z;
    const __half* Bh = Wh + (size_t)(z + zoff) * WSZ;
    float* C = (z == 0) ? C0 : (z == 1) ? C1 : C2;

    int tid = threadIdx.x;
    int wid = tid >> 5, lane = tid & 31;
    int wm = wid & 1, wn = wid >> 1;
    int g = lane >> 2, tq = lane & 3;
    int n0 = blockIdx.x * 128, m0 = blockIdx.y * 128;

    int a_rin = lane & 15;
    uint32_t a_j0 = lane >> 4;
    uint32_t a_t  = (a_rin >> 1) & 3;
    uint32_t a_rowb = (uint32_t)(wm * 64 + a_rin) * 64;

    int b_rin = ((lane >> 4) << 3) + (lane & 7);
    uint32_t b_j0 = (lane >> 3) & 1;
    uint32_t b_t  = (b_rin >> 1) & 3;
    uint32_t b_rowb = (uint32_t)(wn * 32 + b_rin) * 64;

    float acc[4][4][4];
#pragma unroll
    for (int i = 0; i < 4; i++)
#pragma unroll
        for (int j = 0; j < 4; j++)
#pragma unroll
            for (int k = 0; k < 4; k++) acc[i][j][k] = 0.f;

    load_chunk(sb, Ahi, Alo, Bh, m0, n0, 0, tid);
    asm volatile("cp.async.commit_group;" ::: "memory");
    load_chunk(sb + BUF_STRIDE_B, Ahi, Alo, Bh, m0, n0, BK2, tid);
    asm volatile("cp.async.commit_group;" ::: "memory");

    int bufc = 0;
    for (int c = 0; c < NCHUNK2; ++c) {
        if (c + 1 < NCHUNK2) {
            asm volatile("cp.async.wait_group 1;" ::: "memory");
        } else {
            asm volatile("cp.async.wait_group 0;" ::: "memory");
        }
        __syncthreads();

        if (c + 2 < NCHUNK2) {
            int nb = bufc + 2; if (nb >= 3) nb -= 3;
            load_chunk(sb + nb * BUF_STRIDE_B, Ahi, Alo, Bh,
                       m0, n0, (c + 2) * BK2, tid);
            asm volatile("cp.async.commit_group;" ::: "memory");
        }

        uint32_t bufb = sb + bufc * BUF_STRIDE_B;
        uint32_t tAh = bufb;
        uint32_t tAl = bufb + TILE_BYTES;
        uint32_t tBh = bufb + 2 * TILE_BYTES;

#pragma unroll
        for (int ks = 0; ks < 2; ks++) {
            uint32_t aoff = a_rowb + (((a_j0 + 2 * ks) ^ a_t) << 4);
            uint32_t boff = b_rowb + (((b_j0 + 2 * ks) ^ b_t) << 4);

            uint32_t ah[4][4], bh[4][2];
#pragma unroll
            for (int mf = 0; mf < 4; mf++)
                ldsm_x4(ah[mf][0], ah[mf][1], ah[mf][2], ah[mf][3],
                        tAh + mf * (16 * 64) + aoff);
#pragma unroll
            for (int nfp = 0; nfp < 2; nfp++)
                ldsm_x4(bh[2 * nfp][0], bh[2 * nfp][1],
                        bh[2 * nfp + 1][0], bh[2 * nfp + 1][1],
                        tBh + nfp * (16 * 64) + boff);
            // pass 1: Ah * Bh
#pragma unroll
            for (int mf = 0; mf < 4; mf++)
#pragma unroll
                for (int nf = 0; nf < 4; nf++)
                    mma16816h(acc[mf][nf], ah[mf][0], ah[mf][1], ah[mf][2], ah[mf][3],
                              bh[nf][0], bh[nf][1]);
            // pass 2: Al * Bh
            uint32_t al[4][4];
#pragma unroll
            for (int mf = 0; mf < 4; mf++)
                ldsm_x4(al[mf][0], al[mf][1], al[mf][2], al[mf][3],
                        tAl + mf * (16 * 64) + aoff);
#pragma unroll
            for (int mf = 0; mf < 4; mf++)
#pragma unroll
                for (int nf = 0; nf < 4; nf++)
                    mma16816h(acc[mf][nf], al[mf][0], al[mf][1], al[mf][2], al[mf][3],
                              bh[nf][0], bh[nf][1]);
        }
        if (++bufc >= 3) bufc -= 3;
    }

#pragma unroll
    for (int mf = 0; mf < 4; mf++) {
#pragma unroll
        for (int nf = 0; nf < 4; nf++) {
            int row = m0 + wm * 64 + mf * 16 + g;
            int col = n0 + wn * 32 + nf * 8 + 2 * tq;
            float2 v0 = {acc[mf][nf][0], acc[mf][nf][1]};
            float2 v1 = {acc[mf][nf][2], acc[mf][nf][3]};
            *(float2*)&C[(size_t)row * DMODEL + col] = v0;
            *(float2*)&C[(size_t)(row + 8) * DMODEL + col] = v1;
        }
    }
}

// ---------------------------------------------------------------------------
// RoPE + split to head-major bf16 hi/lo for Q and K (attention path)
// ---------------------------------------------------------------------------
__global__ void rope_split_kernel(const float* __restrict__ fcos,
                                  const float* __restrict__ fsin) {
    int p = blockIdx.x * blockDim.x + threadIdx.x;
    int i = p & 63;
    int h = (p >> 6) & 15;
    int s = p >> 10;

    float c  = fcos[s * 64 + i];
    float sn = fsin[s * 64 + i];
    size_t src = (size_t)s * DMODEL + h * HD + 2 * i;
    size_t dst = (size_t)h * (S_LEN * HD) + (size_t)s * HD + 2 * i;

    float q0 = g_Q[src], q1 = g_Q[src + 1];
    float r0 = q0 * c - q1 * sn;
    float r1 = q0 * sn + q1 * c;
    __nv_bfloat16 h0 = __float2bfloat16(r0), h1 = __float2bfloat16(r1);
    *(__nv_bfloat162*)&g_Qh[dst] = {h0, h1};
    *(__nv_bfloat162*)&g_Ql[dst] = {__float2bfloat16(r0 - __bfloat162float(h0)),
                                    __float2bfloat16(r1 - __bfloat162float(h1))};

    float k0 = g_K[src], k1 = g_K[src + 1];
    float t0 = k0 * c - k1 * sn;
    float t1 = k0 * sn + k1 * c;
    __nv_bfloat16 u0 = __float2bfloat16(t0), u1 = __float2bfloat16(t1);
    *(__nv_bfloat162*)&g_Kh[dst] = {u0, u1};
    *(__nv_bfloat162*)&g_Kl[dst] = {__float2bfloat16(t0 - __bfloat162float(u0)),
                                    __float2bfloat16(t1 - __bfloat162float(u1))};
}

// V: [s][h*128+d] fp32 -> Vt [h][d][s] bf16 hi/lo, bf16x2 stores along s.
__global__ void v_split_t_kernel() {
    __shared__ float tile[64][33];
    int s0 = blockIdx.x * 64, d0 = blockIdx.y * 32, h = blockIdx.z;
    int tx = threadIdx.x, ty = threadIdx.y;
#pragma unroll
    for (int r = 0; r < 64; r += 8)
        tile[ty + r][tx] = g_V[(size_t)(s0 + ty + r) * DMODEL + h * HD + d0 + tx];
    __syncthreads();
#pragma unroll
    for (int r = 0; r < 32; r += 8) {
        int d = d0 + ty + r;
        float v0 = tile[2 * tx][ty + r];
        float v1 = tile[2 * tx + 1][ty + r];
        __nv_bfloat16 h0 = __float2bfloat16(v0);
        __nv_bfloat16 h1 = __float2bfloat16(v1);
        size_t o = (size_t)(h * HD + d) * S_LEN + s0 + 2 * tx;
        *(__nv_bfloat162*)&g_Vth[o] = {h0, h1};
        *(__nv_bfloat162*)&g_Vtl[o] = {__float2bfloat16(v0 - __bfloat162float(h0)),
                                       __float2bfloat16(v1 - __bfloat162float(h1))};
    }
}

// ---------------------------------------------------------------------------
// FA2-style HMMA flash attention (R13/R15 shape; epilogue now fp16 hi/lo)
// ---------------------------------------------------------------------------
#define QH_B 0
#define QL_B (64 * 272)
#define KH_B (2 * 64 * 272)
#define KL_B (3 * 64 * 272)
#define VH_B (4 * 64 * 272)
#define VL_B (4 * 64 * 272 + 128 * 144)
#define ATTN_SMEM (4 * 64 * 272 + 2 * 128 * 144)   // 106496 B

__global__ __launch_bounds__(128) void attn_hmma() {
    extern __shared__ char smem[];
    uint32_t sb = smem_u32(smem);

    int tid = threadIdx.x;
    int w = tid >> 5, lane = tid & 31;
    int g = lane >> 2, tq = lane & 3;
    int h = blockIdx.y;
    int qb = gridDim.x - 1 - blockIdx.x;

    const __nv_bfloat16* Qhp = g_Qh + (size_t)h * (S_LEN * HD);
    const __nv_bfloat16* Qlp = g_Ql + (size_t)h * (S_LEN * HD);
    const __nv_bfloat16* Khp = g_Kh + (size_t)h * (S_LEN * HD);
    const __nv_bfloat16* Klp = g_Kl + (size_t)h * (S_LEN * HD);
    const __nv_bfloat16* Vhp = g_Vth + (size_t)h * (HD * S_LEN);
    const __nv_bfloat16* Vlp = g_Vtl + (size_t)h * (HD * S_LEN);

    uint32_t qa_base = (uint32_t)(w * 16 + (lane & 15)) * 272 + (lane >> 4) * 16;
    uint32_t kb_base = (uint32_t)(((lane >> 4) << 3) + (lane & 7)) * 272
                       + ((lane >> 3) & 1) * 16;
    uint32_t vb_base = (uint32_t)(((lane >> 4) << 3) + (lane & 7)) * 144
                       + ((lane >> 3) & 1) * 16;

#pragma unroll
    for (int i = 0; i < 8; i++) {
        int slot = tid + i * 128;
        int row = slot >> 4, j = slot & 15;
        cp16(sb + QH_B + row * 272 + j * 16,
             Qhp + (size_t)(qb * 64 + row) * HD + j * 8);
    }
#pragma unroll
    for (int i = 0; i < 8; i++) {
        int slot = tid + i * 128;
        int row = slot >> 4, j = slot & 15;
        cp16(sb + QL_B + row * 272 + j * 16,
             Qlp + (size_t)(qb * 64 + row) * HD + j * 8);
    }
    asm volatile("cp.async.commit_group;" ::: "memory");

#pragma unroll
    for (int i = 0; i < 8; i++) {
        int slot = tid + i * 128;
        int row = slot >> 4, j = slot & 15;
        cp16(sb + KH_B + row * 272 + j * 16, Khp + (size_t)row * HD + j * 8);
    }
#pragma unroll
    for (int i = 0; i < 8; i++) {
        int slot = tid + i * 128;
        int row = slot >> 4, j = slot & 15;
        cp16(sb + KL_B + row * 272 + j * 16, Klp + (size_t)row * HD + j * 8);
    }
    asm volatile("cp.async.commit_group;" ::: "memory");
#pragma unroll
    for (int i = 0; i < 8; i++) {
        int slot = tid + i * 128;
        int row = slot >> 3, j = slot & 7;
        cp16(sb + VH_B + row * 144 + j * 16, Vhp + (size_t)row * S_LEN + j * 8);
    }
#pragma unroll
    for (int i = 0; i < 8; i++) {
        int slot = tid + i * 128;
        int row = slot >> 3, j = slot & 7;
        cp16(sb + VL_B + row * 144 + j * 16, Vlp + (size_t)row * S_LEN + j * 8);
    }
    asm volatile("cp.async.commit_group;" ::: "memory");

    float of[16][4];
#pragma unroll
    for (int i = 0; i < 16; i++)
#pragma unroll
        for (int j = 0; j < 4; j++) of[i][j] = 0.f;
    float m0 = -INFINITY, m1 = -INFINITY, l0 = 0.f, l1 = 0.f;

    const float inv_sqrt_hd = 0.08838834764831845f;
    const int qrow0 = qb * 64 + w * 16 + g;
    const int qrow1 = qrow0 + 8;

    for (int kb = 0; kb <= qb; ++kb) {
        asm volatile("cp.async.wait_group 1;" ::: "memory");
        __syncthreads();

        float sf[8][4];
#pragma unroll
        for (int i = 0; i < 8; i++)
#pragma unroll
            for (int j = 0; j < 4; j++) sf[i][j] = 0.f;

#pragma unroll
        for (int ks = 0; ks < 8; ks++) {
            uint32_t koff = ks * 32;
            uint32_t ah[4], al[4], bh[8][2], bl[8][2];
            ldsm_x4(ah[0], ah[1], ah[2], ah[3], sb + QH_B + qa_base + koff);
            ldsm_x4(al[0], al[1], al[2], al[3], sb + QL_B + qa_base + koff);
#pragma unroll
            for (int nfp = 0; nfp < 4; nfp++)
                ldsm_x4(bh[2 * nfp][0], bh[2 * nfp][1],
                        bh[2 * nfp + 1][0], bh[2 * nfp + 1][1],
                        sb + KH_B + nfp * (16 * 272) + kb_base + koff);
#pragma unroll
            for (int nfp = 0; nfp < 4; nfp++)
                ldsm_x4(bl[2 * nfp][0], bl[2 * nfp][1],
                        bl[2 * nfp + 1][0], bl[2 * nfp + 1][1],
                        sb + KL_B + nfp * (16 * 272) + kb_base + koff);
#pragma unroll
            for (int nf = 0; nf < 8; nf++)
                mma16816(sf[nf], ah[0], ah[1], ah[2], ah[3], bh[nf][0], bh[nf][1]);
#pragma unroll
            for (int nf = 0; nf < 8; nf++)
                mma16816(sf[nf], ah[0], ah[1], ah[2], ah[3], bl[nf][0], bl[nf][1]);
#pragma unroll
            for (int nf = 0; nf < 8; nf++)
                mma16816(sf[nf], al[0], al[1], al[2], al[3], bh[nf][0], bh[nf][1]);
        }
        __syncthreads();

        if (kb + 1 <= qb) {
#pragma unroll
            for (int i = 0; i < 8; i++) {
                int slot = tid + i * 128;
                int row = slot >> 4, j = slot & 15;
                cp16(sb + KH_B + row * 272 + j * 16,
                     Khp + (size_t)((kb + 1) * 64 + row) * HD + j * 8);
            }
#pragma unroll
            for (int i = 0; i < 8; i++) {
                int slot = tid + i * 128;
                int row = slot >> 4, j = slot & 15;
                cp16(sb + KL_B + row * 272 + j * 16,
                     Klp + (size_t)((kb + 1) * 64 + row) * HD + j * 8);
            }
        }
        asm volatile("cp.async.commit_group;" ::: "memory");

        float mloc0 = -INFINITY, mloc1 = -INFINITY;
        bool diag = (kb == qb);
#pragma unroll
        for (int nf = 0; nf < 8; nf++) {
#pragma unroll
            for (int cc = 0; cc < 2; cc++) {
                int kcol = kb * 64 + nf * 8 + 2 * tq + cc;
                float s = sf[nf][cc] * inv_sqrt_hd;
                float t = s * s * 0.0004f;
                s = s * (1.f - t * (0.3333333333f - 0.1333333333f * t));
                if (diag && kcol > qrow0) s = -INFINITY;
                sf[nf][cc] = s;
                mloc0 = fmaxf(mloc0, s);
                float s2 = sf[nf][cc + 2] * inv_sqrt_hd;
                float t2 = s2 * s2 * 0.0004f;
                s2 = s2 * (1.f - t2 * (0.3333333333f - 0.1333333333f * t2));
                if (diag && kcol > qrow1) s2 = -INFINITY;
                sf[nf][cc + 2] = s2;
                mloc1 = fmaxf(mloc1, s2);
            }
        }
        mloc0 = fmaxf(mloc0, __shfl_xor_sync(0xFFFFFFFF, mloc0, 1));
        mloc0 = fmaxf(mloc0, __shfl_xor_sync(0xFFFFFFFF, mloc0, 2));
        mloc1 = fmaxf(mloc1, __shfl_xor_sync(0xFFFFFFFF, mloc1, 1));
        mloc1 = fmaxf(mloc1, __shfl_xor_sync(0xFFFFFFFF, mloc1, 2));

        float mn0 = fmaxf(m0, mloc0), mn1 = fmaxf(m1, mloc1);
        float cf0 = __expf(m0 - mn0), cf1 = __expf(m1 - mn1);
        m0 = mn0; m1 = mn1;

        float ls0 = 0.f, ls1 = 0.f;
#pragma unroll
        for (int nf = 0; nf < 8; nf++) {
#pragma unroll
            for (int cc = 0; cc < 2; cc++) {
                float p = __expf(sf[nf][cc] - mn0);
                sf[nf][cc] = p; ls0 += p;
                float p2 = __expf(sf[nf][cc + 2] - mn1);
                sf[nf][cc + 2] = p2; ls1 += p2;
            }
        }
        ls0 += __shfl_xor_sync(0xFFFFFFFF, ls0, 1);
        ls0 += __shfl_xor_sync(0xFFFFFFFF, ls0, 2);
        ls1 += __shfl_xor_sync(0xFFFFFFFF, ls1, 1);
        ls1 += __shfl_xor_sync(0xFFFFFFFF, ls1, 2);
        l0 = l0 * cf0 + ls0;
        l1 = l1 * cf1 + ls1;

#pragma unroll
        for (int i = 0; i < 16; i++) {
            of[i][0] *= cf0; of[i][1] *= cf0;
            of[i][2] *= cf1; of[i][3] *= cf1;
        }

        asm volatile("cp.async.wait_group 1;" ::: "memory");
        __syncthreads();

#pragma unroll
        for (int ksv = 0; ksv < 4; ksv++) {
            float c00 = sf[2 * ksv][0],     c01 = sf[2 * ksv][1];
            float c02 = sf[2 * ksv][2],     c03 = sf[2 * ksv][3];
            float c10 = sf[2 * ksv + 1][0], c11 = sf[2 * ksv + 1][1];
            float c12 = sf[2 * ksv + 1][2], c13 = sf[2 * ksv + 1][3];
            uint32_t pa0 = pack_bf16(c00, c01);
            uint32_t pa1 = pack_bf16(c02, c03);
            uint32_t pa2 = pack_bf16(c10, c11);
            uint32_t pa3 = pack_bf16(c12, c13);
            uint32_t pl0 = pack_bf16(c00 - bf16lo_f(pa0), c01 - bf16hi_f(pa0));
            uint32_t pl1 = pack_bf16(c02 - bf16lo_f(pa1), c03 - bf16hi_f(pa1));
            uint32_t pl2 = pack_bf16(c10 - bf16lo_f(pa2), c11 - bf16hi_f(pa2));
            uint32_t pl3 = pack_bf16(c12 - bf16lo_f(pa3), c13 - bf16hi_f(pa3));
            uint32_t soff = ksv * 32;
#pragma unroll
            for (int np = 0; np < 4; np++) {
                int n0i = 2 * np;
                uint32_t vhA0, vhA1, vhA2, vhA3, vlA0, vlA1, vlA2, vlA3;
                uint32_t vhB0, vhB1, vhB2, vhB3, vlB0, vlB1, vlB2, vlB3;
                ldsm_x4(vhA0, vhA1, vhA2, vhA3,
                        sb + VH_B + n0i * (16 * 144) + vb_base + soff);
                ldsm_x4(vlA0, vlA1, vlA2, vlA3,
                        sb + VL_B + n0i * (16 * 144) + vb_base + soff);
                ldsm_x4(vhB0, vhB1, vhB2, vhB3,
                        sb + VH_B + (n0i + 1) * (16 * 144) + vb_base + soff);
                ldsm_x4(vlB0, vlB1, vlB2, vlB3,
                        sb + VL_B + (n0i + 1) * (16 * 144) + vb_base + soff);
                float* oA0 = of[2 * n0i];
                float* oA1 = of[2 * n0i + 1];
                float* oB0 = of[2 * n0i + 2];
                float* oB1 = of[2 * n0i + 3];
                mma16816(oA0, pa0, pa1, pa2, pa3, vhA0, vhA1);
                mma16816(oA1, pa0, pa1, pa2, pa3, vhA2, vhA3);
                mma16816(oB0, pa0, pa1, pa2, pa3, vhB0, vhB1);
                mma16816(oB1, pa0, pa1, pa2, pa3, vhB2, vhB3);
                mma16816(oA0, pa0, pa1, pa2, pa3, vlA0, vlA1);
                mma16816(oA1, pa0, pa1, pa2, pa3, vlA2, vlA3);
                mma16816(oB0, pa0, pa1, pa2, pa3, vlB0, vlB1);
                mma16816(oB1, pa0, pa1, pa2, pa3, vlB2, vlB3);
                mma16816(oA0, pl0, pl1, pl2, pl3, vhA0, vhA1);
                mma16816(oA1, pl0, pl1, pl2, pl3, vhA2, vhA3);
                mma16816(oB0, pl0, pl1, pl2, pl3, vhB0, vhB1);
                mma16816(oB1, pl0, pl1, pl2, pl3, vhB2, vhB3);
            }
        }
        __syncthreads();

        if (kb + 1 <= qb) {
#pragma unroll
            for (int i = 0; i < 8; i++) {
                int slot = tid + i * 128;
                int row = slot >> 3, j = slot & 7;
                cp16(sb + VH_B + row * 144 + j * 16,
                     Vhp + (size_t)row * S_LEN + (kb + 1) * 64 + j * 8);
            }
#pragma unroll
            for (int i = 0; i < 8; i++) {
                int slot = tid + i * 128;
                int row = slot >> 3, j = slot & 7;
                cp16(sb + VL_B + row * 144 + j * 16,
                     Vlp + (size_t)row * S_LEN + (kb + 1) * 64 + j * 8);
            }
        }
        asm volatile("cp.async.commit_group;" ::: "memory");
    }

    // normalize + write fp16 hi/lo (feeds O-projection fp16 GEMM)
    float il0 = 1.f / l0, il1 = 1.f / l1;
#pragma unroll
    for (int nf2 = 0; nf2 < 16; nf2++) {
        int col = h * HD + nf2 * 8 + 2 * tq;
        float o00 = of[nf2][0] * il0, o01 = of[nf2][1] * il0;
        float o10 = of[nf2][2] * il1, o11 = of[nf2][3] * il1;
        __half h00 = __float2half(o00), h01 = __float2half(o01);
        __half h10 = __float2half(o10), h11 = __float2half(o11);
        *(__half2*)&g_ohi[(size_t)qrow0 * DMODEL + col] = {h00, h01};
        *(__half2*)&g_ohi[(size_t)qrow1 * DMODEL + col] = {h10, h11};
        *(__half2*)&g_olo[(size_t)qrow0 * DMODEL + col] =
            {__float2half(o00 - __half2float(h00)),
             __float2half(o01 - __half2float(h01))};
        *(__half2*)&g_olo[(size_t)qrow1 * DMODEL + col] =
            {__float2half(o10 - __half2float(h10)),
             __float2half(o11 - __half2float(h11))};
    }
}

// ---------------------------------------------------------------------------
// Launch
// ---------------------------------------------------------------------------
extern "C" void kernel_launch(void* const* d_in, const int* in_sizes, int n_in,
                              void* d_out, int out_size) {
    const float* x    = (const float*)d_in[0];
    const float* wq   = (const float*)d_in[1];
    const float* wk   = (const float*)d_in[2];
    const float* wv   = (const float*)d_in[3];
    const float* wo   = (const float*)d_in[4];
    const float* fcos = (const float*)d_in[5];
    const float* fsin = (const float*)d_in[6];
    float* out = (float*)d_out;

    float *Qp, *Kp, *Vp;
    __half *xhi, *xlo, *ohi, *olo, *wth;
    cudaGetSymbolAddress((void**)&Qp, g_Q);
    cudaGetSymbolAddress((void**)&Kp, g_K);
    cudaGetSymbolAddress((void**)&Vp, g_V);
    cudaGetSymbolAddress((void**)&xhi, g_xhi);
    cudaGetSymbolAddress((void**)&xlo, g_xlo);
    cudaGetSymbolAddress((void**)&ohi, g_ohi);
    cudaGetSymbolAddress((void**)&olo, g_olo);
    cudaGetSymbolAddress((void**)&wth, g_wth);

    cudaFuncSetAttribute(gemm_hmma, cudaFuncAttributeMaxDynamicSharedMemorySize, GEMM_SMEM);
    cudaFuncSetAttribute(attn_hmma, cudaFuncAttributeMaxDynamicSharedMemorySize, ATTN_SMEM);

    int nElem = S_LEN * DMODEL;

    split_kernel<<<nElem / (256 * 4), 256>>>(x, xhi, xlo);
    wt_split4_kernel<<<dim3(DMODEL / 32, DMODEL / 64, 4), dim3(32, 8)>>>(
        wq, wk, wv, wo, wth);

    gemm_hmma<<<dim3(DMODEL / 128, DMODEL / 128, 3), 256, GEMM_SMEM>>>(
        xhi, xlo, wth, Qp, Kp, Vp, 0);

    int pairs = S_LEN * NH * (HD / 2);
    rope_split_kernel<<<pairs / 256, 256>>>(fcos, fsin);
    v_split_t_kernel<<<dim3(S_LEN / 64, HD / 32, NH), dim3(32, 8)>>>();

    attn_hmma<<<dim3(S_LEN / 64, NH), 128, ATTN_SMEM>>>();

    gemm_hmma<<<dim3(DMODEL / 128, DMODEL / 128, 1), 256, GEMM_SMEM>>>(
        ohi, olo, wth, out, out, out, 3);
}